// round 7
// baseline (speedup 1.0000x reference)
#include <cuda_runtime.h>
#include <cuda_fp16.h>
#include <math.h>

// ---------------------------------------------------------------------------
// Encoder_conv2: 5-level grid encoder, fused single kernel.
//   per level: a = tanh(depthwise_conv3x3(F)); out_l = sum_cell bilinear(a[cell], p+0.5*cell)
// Merged half-integer-lattice trick: G[(2r)^2][4ch] per level in smem.
// Grids: scaled fp16, TWO parity copies of 16-byte corner-PAIR chunks
// (copy A = texels (2j,2j+1), copy B = (2j+1,2j+2)) -> bilinear fetch is
// exactly 2 aligned LDS.128. Thread-per-point, all 5 levels unrolled with
// compile-time constants -> 10 independent LDS in flight. Output goes through
// a per-warp smem transpose (conflict-free) so STG.128 is fully coalesced.
// ---------------------------------------------------------------------------

#define NTHR 768

// a texels cumulative: 2*r*r per level (r = 8,12,20,18,32)
#define ATEXT 3912
// per-level grid byte bases: level l occupies (2r)^2 * 16 bytes (2 copies x 8B)
#define GBT 125184

#define SA_OFF    GBT
#define SA_BYTES  (ATEXT * 16)             // 62592: conv scratch, then warp staging
#define SMEM_BYTES (SA_OFF + SA_BYTES)     // 187776

#define SCALE_UP 1024.0f
#define SCALE_DN (1.0f / 1024.0f)

// per-level compile-time constants
__device__ __constant__ int c_dummy;   // (unused)
#define N2_(l)   ((l)==0?16:(l)==1?24:(l)==2?40:(l)==3?36:64)
#define LB_(l)   ((l)==0?0:(l)==1?4096:(l)==2?13312:(l)==3?38912:59648)

__global__ void __launch_bounds__(NTHR, 1)
k_fused(const float* __restrict__ F0, const float* __restrict__ F1,
        const float* __restrict__ F2, const float* __restrict__ F3,
        const float* __restrict__ F4, const float* __restrict__ W,
        const float* __restrict__ X, const float* __restrict__ Y,
        float* __restrict__ out, int npts) {
    extern __shared__ unsigned char smraw[];
    float4* sa = reinterpret_cast<float4*>(smraw + SA_OFF);   // conv scratch

    const int tid = threadIdx.x;

    const float* Fs[5] = {F0, F1, F2, F3, F4};
    const int resa [5] = {8, 12, 20, 18, 32};
    const int acum [6] = {0, 128, 416, 1216, 1864, 3912};
    const int gbyte[5] = {0, 4096, 13312, 38912, 59648};

    // conv weights (broadcast)
    float w[36];
    #pragma unroll
    for (int i = 0; i < 36; i++) w[i] = W[i];

    // ---- Phase 1a: depthwise conv3x3 (SAME, zero-pad) + tanh -> sa (f32) ----
    for (int tex = tid; tex < ATEXT; tex += NTHR) {
        int l = 0;
        #pragma unroll
        for (int q = 0; q < 4; q++) if (tex >= acum[q + 1]) l = q + 1;
        const float* Fl = Fs[l];
        const int r = resa[l];
        int rem = tex - acum[l];
        int rr  = r * r;
        int j   = rem / rr;
        int yx  = rem - j * rr;
        int y   = yx / r;
        int x   = yx - y * r;

        float oc[4];
        #pragma unroll
        for (int c = 0; c < 4; c++) {
            float s = 0.f;
            #pragma unroll
            for (int dy = 0; dy < 3; dy++) {
                int yy = y + dy - 1;
                if (yy < 0 || yy >= r) continue;
                #pragma unroll
                for (int dx = 0; dx < 3; dx++) {
                    int xx = x + dx - 1;
                    if (xx < 0 || xx >= r) continue;
                    s += __ldg(&Fl[((j * 4 + c) * r + yy) * r + xx]) * w[c * 9 + dy * 3 + dx];
                }
            }
            oc[c] = tanhf(s);
        }
        sa[tex] = make_float4(oc[0], oc[1], oc[2], oc[3]);
    }
    __syncthreads();

    // ---- Phase 1b: merged half-lattice node grids -> packed fp16 pair copies ----
    {
        const int ncum[6] = {0, 256, 832, 2432, 3728, 7824};
        for (int tex = tid; tex < 7824; tex += NTHR) {
            int l = 0;
            #pragma unroll
            for (int q = 0; q < 4; q++) if (tex >= ncum[q + 1]) l = q + 1;
            const int r  = resa[l];
            const int rr = r * r;
            const int n2 = 2 * r;
            int rem = tex - ncum[l];
            int k   = rem / n2;
            int m   = rem - k * n2;

            float ax = 0.f, ay = 0.f, az = 0.f, aw = 0.f;
            #pragma unroll
            for (int j = 0; j < 2; j++) {
                float px = 0.5f * (float)(m + j);
                float py = 0.5f * (float)(k + j);
                float fx = floorf(px), fy = floorf(py);
                float wx = px - fx,    wy = py - fy;
                int ix0 = (int)fx, iy0 = (int)fy;
                int x0 = min(max(ix0,     0), r - 1);
                int x1 = min(max(ix0 + 1, 0), r - 1);
                int y0 = min(max(iy0,     0), r - 1);
                int y1 = min(max(iy0 + 1, 0), r - 1);
                int base = acum[l] + j * rr;
                float4 c00 = sa[base + y0 * r + x0];
                float4 c01 = sa[base + y0 * r + x1];
                float4 c10 = sa[base + y1 * r + x0];
                float4 c11 = sa[base + y1 * r + x1];
                float w00 = (1.f - wx) * (1.f - wy);
                float w01 = wx * (1.f - wy);
                float w10 = (1.f - wx) * wy;
                float w11 = wx * wy;
                ax += c00.x * w00 + c01.x * w01 + c10.x * w10 + c11.x * w11;
                ay += c00.y * w00 + c01.y * w01 + c10.y * w10 + c11.y * w11;
                az += c00.z * w00 + c01.z * w01 + c10.z * w10 + c11.z * w11;
                aw += c00.w * w00 + c01.w * w01 + c10.w * w10 + c11.w * w11;
            }
            __half2 h01 = __floats2half2_rn(ax * SCALE_UP, ay * SCALE_UP);
            __half2 h23 = __floats2half2_rn(az * SCALE_UP, aw * SCALE_UP);
            uint2 val;
            val.x = *reinterpret_cast<unsigned int*>(&h01);
            val.y = *reinterpret_cast<unsigned int*>(&h23);

            const int rowb  = n2 * 8;
            const int asize = n2 * n2 * 8;
            unsigned char* lb = smraw + gbyte[l];
            *reinterpret_cast<uint2*>(lb + k * rowb + m * 8) = val;          // copy A
            if (m >= 1)
                *reinterpret_cast<uint2*>(lb + asize + k * rowb + (m - 1) * 8) = val; // copy B
        }
    }
    __syncthreads();

    // ---- Phase 2: thread-per-point; 10 independent LDS; warp-transposed stores ----
    const int warpid = tid >> 5;
    const int lane   = tid & 31;
    float4* wst = reinterpret_cast<float4*>(smraw + SA_OFF) + warpid * 160; // 32*5 f4
    float4* og  = reinterpret_cast<float4*>(out);

    const int gstride = gridDim.x * NTHR;
    for (int p0 = blockIdx.x * NTHR; p0 < npts; p0 += gstride) {
        int p = p0 + tid;
        if (p < npts) {
            float hx = __ldg(&X[p]);   // x in [0,1): doubled lattice coord h = x*(2r-2)
            float hy = __ldg(&Y[p]);

            uint4 t0[5], t1[5];
            float wxv[5], wyv[5];
            #pragma unroll
            for (int l = 0; l < 5; l++) {
                const int n2       = N2_(l);
                const unsigned rowb  = (unsigned)(n2 * 8);
                const unsigned asize = (unsigned)(n2 * n2 * 8);
                const unsigned lbase = (unsigned)LB_(l);
                const float sx = (float)(n2 - 2);

                float h = hx * sx;
                float v = hy * sx;
                float fm = floorf(h), fk = floorf(v);
                int m0 = (int)fm, k0 = (int)fk;     // in-range, no clamps
                wxv[l] = h - fm;
                wyv[l] = v - fk;

                unsigned addr = lbase + (unsigned)(m0 & 1) * asize
                              + (unsigned)k0 * rowb + (unsigned)(m0 & ~1) * 8u;
                t0[l] = *reinterpret_cast<const uint4*>(smraw + addr);
                t1[l] = *reinterpret_cast<const uint4*>(smraw + addr + rowb);
            }

            #pragma unroll
            for (int l = 0; l < 5; l++) {
                float2 a00 = __half22float2(*reinterpret_cast<__half2*>(&t0[l].x));
                float2 b00 = __half22float2(*reinterpret_cast<__half2*>(&t0[l].y));
                float2 a01 = __half22float2(*reinterpret_cast<__half2*>(&t0[l].z));
                float2 b01 = __half22float2(*reinterpret_cast<__half2*>(&t0[l].w));
                float2 a10 = __half22float2(*reinterpret_cast<__half2*>(&t1[l].x));
                float2 b10 = __half22float2(*reinterpret_cast<__half2*>(&t1[l].y));
                float2 a11 = __half22float2(*reinterpret_cast<__half2*>(&t1[l].z));
                float2 b11 = __half22float2(*reinterpret_cast<__half2*>(&t1[l].w));

                float wx = wxv[l], wy = wyv[l];
                float wyS = wy * SCALE_DN;
                float wyB = SCALE_DN - wyS;       // (1-wy)*2^-10 exactly
                float wxb = 1.f - wx;
                float w00 = wxb * wyB;
                float w01 = wx  * wyB;
                float w10 = wxb * wyS;
                float w11 = wx  * wyS;

                float4 o;
                o.x = a00.x * w00 + a01.x * w01 + a10.x * w10 + a11.x * w11;
                o.y = a00.y * w00 + a01.y * w01 + a10.y * w10 + a11.y * w11;
                o.z = b00.x * w00 + b01.x * w01 + b10.x * w10 + b11.x * w11;
                o.w = b00.y * w00 + b01.y * w01 + b10.y * w10 + b11.y * w11;
                wst[lane * 5 + l] = o;            // conflict-free STS.128
            }
        }
        __syncwarp();

        int wbase = p0 + warpid * 32;
        int cnt = npts - wbase;
        if (cnt > 0) {
            cnt = min(cnt, 32) * 5;
            float4* dst = og + (size_t)wbase * 5;
            #pragma unroll
            for (int i = 0; i < 5; i++) {
                int idx = lane + i * 32;
                if (idx < cnt) dst[idx] = wst[idx];   // fully coalesced STG.128
            }
        }
        __syncwarp();
    }
}

// ---------------------------------------------------------------------------
extern "C" void kernel_launch(void* const* d_in, const int* in_sizes, int n_in,
                              void* d_out, int out_size) {
    const float* X = nullptr;
    const float* Yv = nullptr;
    const float* W = nullptr;
    const float* F[5] = {nullptr, nullptr, nullptr, nullptr, nullptr};
    int npts = 0;

    for (int i = 0; i < n_in; i++) {
        int s = in_sizes[i];
        const float* p = (const float*)d_in[i];
        if (s == 36)        W    = p;
        else if (s == 512)  F[0] = p;
        else if (s == 1152) F[1] = p;
        else if (s == 3200) F[2] = p;
        else if (s == 2592) F[3] = p;
        else if (s == 8192) F[4] = p;
        else {
            if (!X) { X = p; npts = s; }
            else     Yv = p;
        }
    }

    static int nsm = 0;
    static bool init_done = false;
    if (!init_done) {
        cudaFuncSetAttribute(k_fused, cudaFuncAttributeMaxDynamicSharedMemorySize, SMEM_BYTES);
        cudaDeviceGetAttribute(&nsm, cudaDevAttrMultiProcessorCount, 0);
        if (nsm <= 0) nsm = 148;
        init_done = true;
    }

    k_fused<<<nsm, NTHR, SMEM_BYTES>>>(F[0], F[1], F[2], F[3], F[4], W,
                                       X, Yv, (float*)d_out, npts);
}

// round 8
// speedup vs baseline: 1.0761x; 1.0761x over previous
#include <cuda_runtime.h>
#include <cuda_fp16.h>
#include <math.h>

// ---------------------------------------------------------------------------
// Encoder_conv2: 5-level grid encoder, two kernels.
//  k_prep  (1 block): conv3x3+tanh -> merged half-int-lattice grids -> packed
//                     fp16 parity-pair copies -> g_G (gmem, 125 KB). Runs once.
//  k_sample (148 blocks): copy g_G -> smem (coalesced), then thread-per-point
//                     sampling: per level one aligned 2x LDS.128 bilinear fetch.
// Pair layout per level: copy A = texel pairs (2j,2j+1), copy B = (2j+1,2j+2);
// corners (m0,m0+1) are one 16B chunk at (m0&1 ? B : A) + k*rowb + (m0&~1)*8.
// Values scaled by 2^10 into fp16; 2^-10 folded exactly into blend weights.
// ---------------------------------------------------------------------------

#define ATEXT 3912         // sum 2*r*r, r in {8,12,20,18,32}
#define GBT   125184       // sum (2r)^2 * 16 bytes (2 copies x 8B texel)

#define SCALE_UP 1024.0f
#define SCALE_DN (1.0f / 1024.0f)

// per-level compile-time constants (n2 = 2r, byte base of level in packed blob)
#define N2_(l)   ((l)==0?16:(l)==1?24:(l)==2?40:(l)==3?36:64)
#define LB_(l)   ((l)==0?0:(l)==1?4096:(l)==2?13312:(l)==3?38912:59648)

__device__ uint2 g_G[GBT / 8];   // packed grids, built once by k_prep

// ---------------------------------------------------------------------------
// k_prep: one block, 1024 threads. smem = f32 conv scratch (62592 B).
// ---------------------------------------------------------------------------
__global__ void __launch_bounds__(1024, 1)
k_prep(const float* __restrict__ F0, const float* __restrict__ F1,
       const float* __restrict__ F2, const float* __restrict__ F3,
       const float* __restrict__ F4, const float* __restrict__ W) {
    extern __shared__ float4 sa[];   // ATEXT float4
    const int tid = threadIdx.x;

    const float* Fs[5] = {F0, F1, F2, F3, F4};
    const int resa [5] = {8, 12, 20, 18, 32};
    const int acum [6] = {0, 128, 416, 1216, 1864, 3912};
    const int gbyte[5] = {0, 4096, 13312, 38912, 59648};

    float w[36];
    #pragma unroll
    for (int i = 0; i < 36; i++) w[i] = W[i];

    // conv3x3 (SAME, zero pad) + tanh
    for (int tex = tid; tex < ATEXT; tex += 1024) {
        int l = 0;
        #pragma unroll
        for (int q = 0; q < 4; q++) if (tex >= acum[q + 1]) l = q + 1;
        const float* Fl = Fs[l];
        const int r = resa[l];
        int rem = tex - acum[l];
        int rr  = r * r;
        int j   = rem / rr;
        int yx  = rem - j * rr;
        int y   = yx / r;
        int x   = yx - y * r;

        float oc[4];
        #pragma unroll
        for (int c = 0; c < 4; c++) {
            float s = 0.f;
            #pragma unroll
            for (int dy = 0; dy < 3; dy++) {
                int yy = y + dy - 1;
                if (yy < 0 || yy >= r) continue;
                #pragma unroll
                for (int dx = 0; dx < 3; dx++) {
                    int xx = x + dx - 1;
                    if (xx < 0 || xx >= r) continue;
                    s += __ldg(&Fl[((j * 4 + c) * r + yy) * r + xx]) * w[c * 9 + dy * 3 + dx];
                }
            }
            oc[c] = tanhf(s);
        }
        sa[tex] = make_float4(oc[0], oc[1], oc[2], oc[3]);
    }
    __syncthreads();

    // merged half-lattice nodes -> packed fp16 parity-pair copies in gmem
    const int ncum[6] = {0, 256, 832, 2432, 3728, 7824};
    for (int tex = tid; tex < 7824; tex += 1024) {
        int l = 0;
        #pragma unroll
        for (int q = 0; q < 4; q++) if (tex >= ncum[q + 1]) l = q + 1;
        const int r  = resa[l];
        const int rr = r * r;
        const int n2 = 2 * r;
        int rem = tex - ncum[l];
        int k   = rem / n2;
        int m   = rem - k * n2;

        float ax = 0.f, ay = 0.f, az = 0.f, aw = 0.f;
        #pragma unroll
        for (int j = 0; j < 2; j++) {
            float px = 0.5f * (float)(m + j);
            float py = 0.5f * (float)(k + j);
            float fx = floorf(px), fy = floorf(py);
            float wx = px - fx,    wy = py - fy;
            int ix0 = (int)fx, iy0 = (int)fy;
            int x0 = min(max(ix0,     0), r - 1);
            int x1 = min(max(ix0 + 1, 0), r - 1);
            int y0 = min(max(iy0,     0), r - 1);
            int y1 = min(max(iy0 + 1, 0), r - 1);
            int base = acum[l] + j * rr;
            float4 c00 = sa[base + y0 * r + x0];
            float4 c01 = sa[base + y0 * r + x1];
            float4 c10 = sa[base + y1 * r + x0];
            float4 c11 = sa[base + y1 * r + x1];
            float w00 = (1.f - wx) * (1.f - wy);
            float w01 = wx * (1.f - wy);
            float w10 = (1.f - wx) * wy;
            float w11 = wx * wy;
            ax += c00.x * w00 + c01.x * w01 + c10.x * w10 + c11.x * w11;
            ay += c00.y * w00 + c01.y * w01 + c10.y * w10 + c11.y * w11;
            az += c00.z * w00 + c01.z * w01 + c10.z * w10 + c11.z * w11;
            aw += c00.w * w00 + c01.w * w01 + c10.w * w10 + c11.w * w11;
        }
        __half2 h01 = __floats2half2_rn(ax * SCALE_UP, ay * SCALE_UP);
        __half2 h23 = __floats2half2_rn(az * SCALE_UP, aw * SCALE_UP);
        uint2 val;
        val.x = *reinterpret_cast<unsigned int*>(&h01);
        val.y = *reinterpret_cast<unsigned int*>(&h23);

        const int rowe  = n2;                 // texels per row
        const int asize = n2 * n2;            // texels per copy
        uint2* lb = g_G + gbyte[l] / 8;
        lb[k * rowe + m] = val;                               // copy A
        if (m >= 1) lb[asize + k * rowe + (m - 1)] = val;     // copy B
    }
}

// ---------------------------------------------------------------------------
// k_sample: smem = packed grids (125184 B). Thread-per-point.
// ---------------------------------------------------------------------------
#define NTHR 1024

__global__ void __launch_bounds__(NTHR, 1)
k_sample(const float* __restrict__ X, const float* __restrict__ Y,
         float* __restrict__ out, int npts) {
    extern __shared__ unsigned char smraw[];
    const int tid = threadIdx.x;

    // coalesced copy of packed grids: 7824 uint4
    {
        const uint4* src = reinterpret_cast<const uint4*>(g_G);
        uint4* dst = reinterpret_cast<uint4*>(smraw);
        for (int i = tid; i < GBT / 16; i += NTHR) dst[i] = src[i];
    }
    __syncthreads();

    const int stride = gridDim.x * NTHR;
    for (int p = blockIdx.x * NTHR + tid; p < npts; p += stride) {
        float hx = __ldg(&X[p]);   // x in [0,1): doubled lattice coord h = x*(2r-2)
        float hy = __ldg(&Y[p]);
        float* outp = out + (size_t)p * 20;

        #pragma unroll
        for (int l = 0; l < 5; l++) {
            const int n2         = N2_(l);
            const unsigned rowb  = (unsigned)(n2 * 8);
            const unsigned asize = (unsigned)(n2 * n2 * 8);
            const unsigned lbase = (unsigned)LB_(l);
            const float sx = (float)(n2 - 2);

            float h = hx * sx;
            float v = hy * sx;
            float fm = floorf(h), fk = floorf(v);
            int m0 = (int)fm, k0 = (int)fk;      // in-range, no clamps needed
            float wx = h - fm, wy = v - fk;

            unsigned addr = lbase + (unsigned)(m0 & 1) * asize
                          + (unsigned)k0 * rowb + (unsigned)(m0 & ~1) * 8u;
            uint4 t0 = *reinterpret_cast<const uint4*>(smraw + addr);         // c00,c01
            uint4 t1 = *reinterpret_cast<const uint4*>(smraw + addr + rowb);  // c10,c11

            float2 a00 = __half22float2(*reinterpret_cast<__half2*>(&t0.x));
            float2 b00 = __half22float2(*reinterpret_cast<__half2*>(&t0.y));
            float2 a01 = __half22float2(*reinterpret_cast<__half2*>(&t0.z));
            float2 b01 = __half22float2(*reinterpret_cast<__half2*>(&t0.w));
            float2 a10 = __half22float2(*reinterpret_cast<__half2*>(&t1.x));
            float2 b10 = __half22float2(*reinterpret_cast<__half2*>(&t1.y));
            float2 a11 = __half22float2(*reinterpret_cast<__half2*>(&t1.z));
            float2 b11 = __half22float2(*reinterpret_cast<__half2*>(&t1.w));

            float wyS = wy * SCALE_DN;
            float wyB = SCALE_DN - wyS;       // (1-wy)*2^-10 exactly
            float wxb = 1.f - wx;
            float w00 = wxb * wyB;
            float w01 = wx  * wyB;
            float w10 = wxb * wyS;
            float w11 = wx  * wyS;

            float4 o;
            o.x = a00.x * w00 + a01.x * w01 + a10.x * w10 + a11.x * w11;
            o.y = a00.y * w00 + a01.y * w01 + a10.y * w10 + a11.y * w11;
            o.z = b00.x * w00 + b01.x * w01 + b10.x * w10 + b11.x * w11;
            o.w = b00.y * w00 + b01.y * w01 + b10.y * w10 + b11.y * w11;

            *reinterpret_cast<float4*>(outp + l * 4) = o;   // 16B-aligned (80B rows)
        }
    }
}

// ---------------------------------------------------------------------------
extern "C" void kernel_launch(void* const* d_in, const int* in_sizes, int n_in,
                              void* d_out, int out_size) {
    const float* X = nullptr;
    const float* Yv = nullptr;
    const float* W = nullptr;
    const float* F[5] = {nullptr, nullptr, nullptr, nullptr, nullptr};
    int npts = 0;

    for (int i = 0; i < n_in; i++) {
        int s = in_sizes[i];
        const float* p = (const float*)d_in[i];
        if (s == 36)        W    = p;
        else if (s == 512)  F[0] = p;
        else if (s == 1152) F[1] = p;
        else if (s == 3200) F[2] = p;
        else if (s == 2592) F[3] = p;
        else if (s == 8192) F[4] = p;
        else {
            if (!X) { X = p; npts = s; }
            else     Yv = p;
        }
    }

    static int nsm = 0;
    static bool init_done = false;
    if (!init_done) {
        cudaFuncSetAttribute(k_prep,   cudaFuncAttributeMaxDynamicSharedMemorySize, ATEXT * 16);
        cudaFuncSetAttribute(k_sample, cudaFuncAttributeMaxDynamicSharedMemorySize, GBT);
        cudaDeviceGetAttribute(&nsm, cudaDevAttrMultiProcessorCount, 0);
        if (nsm <= 0) nsm = 148;
        init_done = true;
    }

    k_prep<<<1, 1024, ATEXT * 16>>>(F[0], F[1], F[2], F[3], F[4], W);
    k_sample<<<nsm, NTHR, GBT>>>(X, Yv, (float*)d_out, npts);
}

// round 9
// speedup vs baseline: 1.4192x; 1.3189x over previous
#include <cuda_runtime.h>
#include <cuda_fp16.h>
#include <math.h>

// ---------------------------------------------------------------------------
// Encoder_conv2: 5-level grid encoder, two kernels.
//  k_prep  (5 blocks, one per level, all constants compile-time):
//     conv3x3+tanh -> smem -> merged half-int-lattice nodes -> packed fp16
//     parity-pair copies -> g_G (gmem, 125 KB).
//  k_sample (148 blocks): copy g_G -> smem, thread-per-point sampling
//     (per level one aligned 2x LDS.128 bilinear fetch), warp-transposed
//     coalesced output stores.
// Pair layout per level: copy A = texel pairs (2j,2j+1), copy B = (2j+1,2j+2);
// corners (m0,m0+1) are one 16B chunk at (m0&1 ? B : A) + k*rowb + (m0&~1)*8.
// Values scaled by 2^10 into fp16; 2^-10 folded exactly into blend weights.
// ---------------------------------------------------------------------------

#define GBT   125184       // sum (2r)^2 * 16 bytes (2 copies x 8B texel)

#define SCALE_UP 1024.0f
#define SCALE_DN (1.0f / 1024.0f)

// per-level compile-time constants (n2 = 2r, byte base of level in packed blob)
#define N2_(l)   ((l)==0?16:(l)==1?24:(l)==2?40:(l)==3?36:64)
#define LB_(l)   ((l)==0?0:(l)==1?4096:(l)==2?13312:(l)==3?38912:59648)

__device__ uint2 g_G[GBT / 8];   // packed grids, built by k_prep

// ---------------------------------------------------------------------------
// k_prep: blockIdx.x = level; fully compile-time constants per level.
// ---------------------------------------------------------------------------
template<int R, int LB>
__device__ __forceinline__ void prep_level(const float* __restrict__ F,
                                           const float* w, float4* sa, int tid) {
    constexpr int RR = R * R;
    constexpr int NA = 2 * RR;

    // conv3x3 (SAME, zero pad, cross-correlation) + tanh -> sa
    for (int tex = tid; tex < NA; tex += 1024) {
        int j  = tex / RR;
        int yx = tex - j * RR;
        int y  = yx / R;
        int x  = yx - y * R;

        float oc[4];
        #pragma unroll
        for (int c = 0; c < 4; c++) {
            float s = 0.f;
            #pragma unroll
            for (int dy = 0; dy < 3; dy++) {
                int yy = y + dy - 1;
                if (yy < 0 || yy >= R) continue;
                #pragma unroll
                for (int dx = 0; dx < 3; dx++) {
                    int xx = x + dx - 1;
                    if (xx < 0 || xx >= R) continue;
                    s += __ldg(&F[((j * 4 + c) * R + yy) * R + xx]) * w[c * 9 + dy * 3 + dx];
                }
            }
            oc[c] = tanhf(s);
        }
        sa[tex] = make_float4(oc[0], oc[1], oc[2], oc[3]);
    }
    __syncthreads();

    // merged half-lattice nodes -> packed fp16 parity-pair copies (gmem)
    constexpr int N2 = 2 * R;
    uint2* lb = g_G + LB / 8;
    for (int tex = tid; tex < N2 * N2; tex += 1024) {
        int k = tex / N2;
        int m = tex - k * N2;

        float ax = 0.f, ay = 0.f, az = 0.f, aw = 0.f;
        #pragma unroll
        for (int j = 0; j < 2; j++) {
            float px = 0.5f * (float)(m + j);
            float py = 0.5f * (float)(k + j);
            float fx = floorf(px), fy = floorf(py);
            float wx = px - fx,    wy = py - fy;
            int ix0 = (int)fx, iy0 = (int)fy;
            int x0 = min(max(ix0,     0), R - 1);
            int x1 = min(max(ix0 + 1, 0), R - 1);
            int y0 = min(max(iy0,     0), R - 1);
            int y1 = min(max(iy0 + 1, 0), R - 1);
            int base = j * RR;
            float4 c00 = sa[base + y0 * R + x0];
            float4 c01 = sa[base + y0 * R + x1];
            float4 c10 = sa[base + y1 * R + x0];
            float4 c11 = sa[base + y1 * R + x1];
            float w00 = (1.f - wx) * (1.f - wy);
            float w01 = wx * (1.f - wy);
            float w10 = (1.f - wx) * wy;
            float w11 = wx * wy;
            ax += c00.x * w00 + c01.x * w01 + c10.x * w10 + c11.x * w11;
            ay += c00.y * w00 + c01.y * w01 + c10.y * w10 + c11.y * w11;
            az += c00.z * w00 + c01.z * w01 + c10.z * w10 + c11.z * w11;
            aw += c00.w * w00 + c01.w * w01 + c10.w * w10 + c11.w * w11;
        }
        __half2 h01 = __floats2half2_rn(ax * SCALE_UP, ay * SCALE_UP);
        __half2 h23 = __floats2half2_rn(az * SCALE_UP, aw * SCALE_UP);
        uint2 val;
        val.x = *reinterpret_cast<unsigned int*>(&h01);
        val.y = *reinterpret_cast<unsigned int*>(&h23);

        lb[k * N2 + m] = val;                                  // copy A
        if (m >= 1) lb[N2 * N2 + k * N2 + (m - 1)] = val;      // copy B
    }
}

__global__ void __launch_bounds__(1024, 1)
k_prep(const float* __restrict__ F0, const float* __restrict__ F1,
       const float* __restrict__ F2, const float* __restrict__ F3,
       const float* __restrict__ F4, const float* __restrict__ W) {
    __shared__ float4 sa[2048];   // largest level: 2*32*32 texels = 32 KB
    const int tid = threadIdx.x;

    float w[36];
    #pragma unroll
    for (int i = 0; i < 36; i++) w[i] = W[i];

    switch (blockIdx.x) {
        case 0: prep_level< 8, LB_(0)>(F0, w, sa, tid); break;
        case 1: prep_level<12, LB_(1)>(F1, w, sa, tid); break;
        case 2: prep_level<20, LB_(2)>(F2, w, sa, tid); break;
        case 3: prep_level<18, LB_(3)>(F3, w, sa, tid); break;
        default: prep_level<32, LB_(4)>(F4, w, sa, tid); break;
    }
}

// ---------------------------------------------------------------------------
// k_sample: smem = packed grids (125184 B) + warp staging (81920 B).
// ---------------------------------------------------------------------------
#define NTHR 1024
#define STAGE_OFF GBT
#define SMEM_SAMPLE (GBT + (NTHR / 32) * 32 * 5 * 16)   // 207104

__global__ void __launch_bounds__(NTHR, 1)
k_sample(const float* __restrict__ X, const float* __restrict__ Y,
         float* __restrict__ out, int npts) {
    extern __shared__ unsigned char smraw[];
    const int tid = threadIdx.x;

    // coalesced copy of packed grids: 7824 uint4
    {
        const uint4* src = reinterpret_cast<const uint4*>(g_G);
        uint4* dst = reinterpret_cast<uint4*>(smraw);
        for (int i = tid; i < GBT / 16; i += NTHR) dst[i] = src[i];
    }
    __syncthreads();

    const int warpid = tid >> 5;
    const int lane   = tid & 31;
    float4* wst = reinterpret_cast<float4*>(smraw + STAGE_OFF) + warpid * 160;
    float4* og  = reinterpret_cast<float4*>(out);

    const int gstride = gridDim.x * NTHR;
    for (int p0 = blockIdx.x * NTHR; p0 < npts; p0 += gstride) {
        int p = p0 + tid;
        if (p < npts) {
            float hx = __ldg(&X[p]);   // x in [0,1): doubled lattice coord h = x*(2r-2)
            float hy = __ldg(&Y[p]);

            #pragma unroll
            for (int l = 0; l < 5; l++) {
                const int n2         = N2_(l);
                const unsigned rowb  = (unsigned)(n2 * 8);
                const unsigned asize = (unsigned)(n2 * n2 * 8);
                const unsigned lbase = (unsigned)LB_(l);
                const float sx = (float)(n2 - 2);

                float h = hx * sx;
                float v = hy * sx;
                float fm = floorf(h), fk = floorf(v);
                int m0 = (int)fm, k0 = (int)fk;      // in-range, no clamps
                float wx = h - fm, wy = v - fk;

                unsigned addr = lbase + (unsigned)(m0 & 1) * asize
                              + (unsigned)k0 * rowb + (unsigned)(m0 & ~1) * 8u;
                uint4 t0 = *reinterpret_cast<const uint4*>(smraw + addr);         // c00,c01
                uint4 t1 = *reinterpret_cast<const uint4*>(smraw + addr + rowb);  // c10,c11

                float2 a00 = __half22float2(*reinterpret_cast<__half2*>(&t0.x));
                float2 b00 = __half22float2(*reinterpret_cast<__half2*>(&t0.y));
                float2 a01 = __half22float2(*reinterpret_cast<__half2*>(&t0.z));
                float2 b01 = __half22float2(*reinterpret_cast<__half2*>(&t0.w));
                float2 a10 = __half22float2(*reinterpret_cast<__half2*>(&t1.x));
                float2 b10 = __half22float2(*reinterpret_cast<__half2*>(&t1.y));
                float2 a11 = __half22float2(*reinterpret_cast<__half2*>(&t1.z));
                float2 b11 = __half22float2(*reinterpret_cast<__half2*>(&t1.w));

                float wyS = wy * SCALE_DN;
                float wyB = SCALE_DN - wyS;       // (1-wy)*2^-10 exactly
                float wxb = 1.f - wx;
                float w00 = wxb * wyB;
                float w01 = wx  * wyB;
                float w10 = wxb * wyS;
                float w11 = wx  * wyS;

                float4 o;
                o.x = a00.x * w00 + a01.x * w01 + a10.x * w10 + a11.x * w11;
                o.y = a00.y * w00 + a01.y * w01 + a10.y * w10 + a11.y * w11;
                o.z = b00.x * w00 + b01.x * w01 + b10.x * w10 + b11.x * w11;
                o.w = b00.y * w00 + b01.y * w01 + b10.y * w10 + b11.y * w11;

                wst[lane * 5 + l] = o;            // conflict-free STS.128
            }
        }
        __syncwarp();

        int wbase = p0 + warpid * 32;
        int cnt = npts - wbase;
        if (cnt > 0) {
            cnt = min(cnt, 32) * 5;
            float4* dst = og + (size_t)wbase * 5;
            #pragma unroll
            for (int i = 0; i < 5; i++) {
                int idx = lane + i * 32;
                if (idx < cnt) dst[idx] = wst[idx];   // fully coalesced STG.128
            }
        }
        __syncwarp();
    }
}

// ---------------------------------------------------------------------------
extern "C" void kernel_launch(void* const* d_in, const int* in_sizes, int n_in,
                              void* d_out, int out_size) {
    const float* X = nullptr;
    const float* Yv = nullptr;
    const float* W = nullptr;
    const float* F[5] = {nullptr, nullptr, nullptr, nullptr, nullptr};
    int npts = 0;

    for (int i = 0; i < n_in; i++) {
        int s = in_sizes[i];
        const float* p = (const float*)d_in[i];
        if (s == 36)        W    = p;
        else if (s == 512)  F[0] = p;
        else if (s == 1152) F[1] = p;
        else if (s == 3200) F[2] = p;
        else if (s == 2592) F[3] = p;
        else if (s == 8192) F[4] = p;
        else {
            if (!X) { X = p; npts = s; }
            else     Yv = p;
        }
    }

    static int nsm = 0;
    static bool init_done = false;
    if (!init_done) {
        cudaFuncSetAttribute(k_sample, cudaFuncAttributeMaxDynamicSharedMemorySize, SMEM_SAMPLE);
        cudaDeviceGetAttribute(&nsm, cudaDevAttrMultiProcessorCount, 0);
        if (nsm <= 0) nsm = 148;
        init_done = true;
    }

    k_prep<<<5, 1024>>>(F[0], F[1], F[2], F[3], F[4], W);
    k_sample<<<nsm, NTHR, SMEM_SAMPLE>>>(X, Yv, (float*)d_out, npts);
}